// round 6
// baseline (speedup 1.0000x reference)
#include <cuda_runtime.h>
#include <cuda_fp8.h>
#include <cuda_fp16.h>
#include <cstdint>
#include <math.h>

#define Bn   16
#define ICn  64
#define OCn  128
#define Hn   224
#define Wn   224
#define HWn  (Hn * Wn)
#define APIX 256                 // pixels per tile (GEMM M)
#define NT2  (HWn / APIX)        // 196 tiles per image
#define NJOBS (NT2 * Bn)         // 3136 tiles total
#define NCTA  296                // persistent CTAs (148 SM x 2)
#define MAXT  11                 // ceil(3136/296)
#define NK    (MAXT * 9)         // 99 linear jobs per CTA
#define NTILES (HWn / 128)       // 392 (prep_x grid)
#define NTAPS 9

// fp8 scratch
__device__ uint8_t g_x8[(size_t)Bn * HWn * ICn];        // [b][hw][ic]
__device__ uint8_t g_w8[NTAPS * 4 * OCn * 16];          // [tap][chunk][oc][16]

__device__ __forceinline__ uint32_t smem_u32(const void* p) {
    uint32_t a;
    asm("{ .reg .u64 t; cvta.to.shared.u64 t, %1; cvt.u32.u64 %0, t; }"
        : "=r"(a) : "l"(p));
    return a;
}

// ---------------- prep kernels ----------------
__global__ void prep_w(const float* __restrict__ Wg) {
    int idx = blockIdx.x * 256 + threadIdx.x;
    if (idx < OCn * ICn * NTAPS) {
        int tap = idx % NTAPS;
        int ic  = (idx / NTAPS) % ICn;
        int oc  = idx / (NTAPS * ICn);
        uint8_t v = (uint8_t)__nv_cvt_float_to_fp8(Wg[idx], __NV_SATFINITE, __NV_E4M3);
        g_w8[((tap * 4 + (ic >> 4)) * OCn + oc) * 16 + (ic & 15)] = v;
    }
}

__global__ __launch_bounds__(256) void prep_x(const float* __restrict__ x) {
    __shared__ uint8_t s[128 * 65];
    const int tile = blockIdx.x, b = blockIdx.y;
    const int hw0 = tile * 128;
    const int t = threadIdx.x;
    const int ic = t >> 2, q = t & 3;

    const float4* src =
        (const float4*)(x + (size_t)b * ICn * HWn + (size_t)ic * HWn + hw0 + q * 32);
#pragma unroll
    for (int j = 0; j < 8; ++j) {
        float4 v = src[j];
        int pix = q * 32 + j * 4;
        s[(pix + 0) * 65 + ic] = (uint8_t)__nv_cvt_float_to_fp8(v.x, __NV_SATFINITE, __NV_E4M3);
        s[(pix + 1) * 65 + ic] = (uint8_t)__nv_cvt_float_to_fp8(v.y, __NV_SATFINITE, __NV_E4M3);
        s[(pix + 2) * 65 + ic] = (uint8_t)__nv_cvt_float_to_fp8(v.z, __NV_SATFINITE, __NV_E4M3);
        s[(pix + 3) * 65 + ic] = (uint8_t)__nv_cvt_float_to_fp8(v.w, __NV_SATFINITE, __NV_E4M3);
    }
    __syncthreads();

    const int pr = t >> 1, half = t & 1;
    uint32_t vv[8];
#pragma unroll
    for (int j = 0; j < 8; ++j) {
        int base = pr * 65 + half * 32 + j * 4;
        vv[j] = (uint32_t)s[base] | ((uint32_t)s[base + 1] << 8) |
                ((uint32_t)s[base + 2] << 16) | ((uint32_t)s[base + 3] << 24);
    }
    uint4* dst = (uint4*)(g_x8 + ((size_t)b * HWn + hw0 + pr) * 64 + half * 32);
    dst[0] = make_uint4(vv[0], vv[1], vv[2], vv[3]);
    dst[1] = make_uint4(vv[4], vv[5], vv[6], vv[7]);
}

// ---------------- main kernel ----------------
__device__ __forceinline__ void ldsm_x4(uint32_t* r, uint32_t addr) {
    asm volatile("ldmatrix.sync.aligned.m8n8.x4.shared.b16 {%0,%1,%2,%3}, [%4];"
                 : "=r"(r[0]), "=r"(r[1]), "=r"(r[2]), "=r"(r[3]) : "r"(addr));
}
__device__ __forceinline__ void qmma_h(uint32_t* d, const uint32_t* a,
                                       uint32_t b0, uint32_t b1) {
    asm volatile(
        "mma.sync.aligned.m16n8k32.row.col.f16.e4m3.e4m3.f16 "
        "{%0,%1}, {%2,%3,%4,%5}, {%6,%7}, {%0,%1};"
        : "+r"(d[0]), "+r"(d[1])
        : "r"(a[0]), "r"(a[1]), "r"(a[2]), "r"(a[3]), "r"(b0), "r"(b1));
}
__device__ __forceinline__ void cp16(uint32_t dst, const void* src, uint32_t sz) {
    asm volatile("cp.async.ca.shared.global [%0], [%1], 16, %2;"
                 :: "r"(dst), "l"(src), "r"(sz) : "memory");
}
__device__ __forceinline__ void cp16g(uint32_t dst, const void* src) {
    asm volatile("cp.async.cg.shared.global [%0], [%1], 16;"
                 :: "r"(dst), "l"(src) : "memory");
}
__device__ __forceinline__ void cp_commit() {
    asm volatile("cp.async.commit_group;" ::: "memory");
}
__device__ __forceinline__ void cp_wait0() {
    asm volatile("cp.async.wait_group 0;" ::: "memory");
}

// smem layout:
//   A: [2][4][APIX][16]        = 32768 B  @ 0
//   B: [9][4][128][16]         = 73728 B  @ 32768   (resident all kernel)
//   bias: 64 x half2           = 256 B    @ 106496
#define SM_A(buf, c, p)  ((uint32_t)(((buf) * 4 + (c)) * APIX + (p)) * 16)
#define SM_B(tap, c, r)  (32768u + (uint32_t)(((tap) * 4 + (c)) * 128 + (r)) * 16)
#define SM_BIAS 106496
#define SM_TOTAL 106752

__global__ __launch_bounds__(256, 2)
void conv_mma(const float* __restrict__ bias, float* __restrict__ out) {
    extern __shared__ __align__(16) uint8_t smem[];
    const __half2* bias_h2 = (const __half2*)(smem + SM_BIAS);

    const int tid = threadIdx.x;
    const int wid = tid >> 5;
    const int lane = tid & 31;
    const uint32_t smem_base = smem_u32(smem);

    const int m0 = wid * 32;
    const int a_chunk_hi = (lane >= 16) ? 1 : 0;
    const int a_row0 = m0 + ((lane >> 3) & 1) * 8 + (lane & 7);
    const int a_row1 = a_row0 + 16;
    const int b_chunk_hi = (lane >> 3) & 1;
    const int b_row_off = ((lane >= 16) ? 8 : 0) + (lane & 7);
    const int s = lane & 3;

    // ---- one-time: bias -> smem (half2), B all 9 taps -> smem ----
    if (tid < 64) {
        float2 bv = ((const float2*)bias)[tid];
        ((__half2*)(smem + SM_BIAS))[tid] = __floats2half2_rn(bv.x, bv.y);
    }
#pragma unroll
    for (int i = 0; i < 18; ++i)
        cp16g(smem_base + 32768u + (uint32_t)(i * 256 + tid) * 16,
              g_w8 + (i * 256 + tid) * 16);
    cp_commit();

    // ---- job state (tile-major, tap-minor linear pipeline) ----
    // current (compute) job
    int gc = blockIdx.x;                 // tile id
    int tapc = 0;
    // next (issue) job
    int gn = blockIdx.x;
    int tapn = 0;
    int hn = 0, wn = 0;
    const uint8_t* xbn = 0;
    {
        if (gn < NJOBS) {
            int pn = (gn % NT2) * APIX + tid;
            hn = pn / Wn; wn = pn - hn * Wn;
            xbn = g_x8 + (size_t)(gn / NT2) * HWn * 64;
        }
    }
    // issue job 0 (buf 0)
    {
        if (gn < NJOBS) {
            const int gh = hn - 1, gw = wn - 1;
            const uint32_t sz = (gh >= 0 && gw >= 0) ? 16u : 0u;
            const uint8_t* sp = xbn + ((size_t)gh * Wn + gw) * 64;
#pragma unroll
            for (int c = 0; c < 4; ++c)
                cp16(smem_base + SM_A(0, c, tid), sp + c * 16, sz);
        }
        cp_commit();
        // advance next -> job 1
        tapn = 1;
    }

    uint32_t d0[16][2], d1[16][2];

#pragma unroll 1
    for (int k = 0; k < NK; ++k) {
        cp_wait0();
        __syncthreads();     // A_k visible; all warps done reading buf (k+1)&1

        // ---- issue job k+1 into buf (k+1)&1 ----
        if (k < NK - 1) {
            if (gn < NJOBS) {
                const int gh = hn + tapn / 3 - 1;
                const int gw = wn + tapn % 3 - 1;
                const uint32_t sz =
                    (gh >= 0 && gh < Hn && gw >= 0 && gw < Wn) ? 16u : 0u;
                const uint8_t* sp = xbn + ((size_t)gh * Wn + gw) * 64;
                const int nbuf = (k + 1) & 1;
#pragma unroll
                for (int c = 0; c < 4; ++c)
                    cp16(smem_base + SM_A(nbuf, c, tid), sp + c * 16, sz);
            }
            // advance next counters
            if (++tapn == 9) {
                tapn = 0;
                gn += NCTA;
                if (gn < NJOBS) {
                    int pn = (gn % NT2) * APIX + tid;
                    hn = pn / Wn; wn = pn - hn * Wn;
                    xbn = g_x8 + (size_t)(gn / NT2) * HWn * 64;
                }
            }
        }
        cp_commit();

        // ---- compute job k ----
        if (gc < NJOBS) {
            if (tapc == 0) {
#pragma unroll
                for (int j = 0; j < 16; ++j) {
                    d0[j][0] = d0[j][1] = 0u;
                    d1[j][0] = d1[j][1] = 0u;
                }
            }
            const int buf = k & 1;
#pragma unroll
            for (int ks = 0; ks < 2; ++ks) {
                uint32_t a0[4], a1[4];
                ldsm_x4(a0, smem_base + SM_A(buf, 2 * ks + a_chunk_hi, a_row0));
                ldsm_x4(a1, smem_base + SM_A(buf, 2 * ks + a_chunk_hi, a_row1));
#pragma unroll
                for (int half = 0; half < 2; ++half) {
                    uint32_t bb[16];
#pragma unroll
                    for (int j2 = 0; j2 < 4; ++j2) {
                        int jj = half * 4 + j2;
                        ldsm_x4(&bb[j2 * 4],
                                smem_base + SM_B(tapc, 2 * ks + b_chunk_hi,
                                                 jj * 16 + b_row_off));
                    }
#pragma unroll
                    for (int j2 = 0; j2 < 4; ++j2) {
                        int jj = half * 4 + j2;
                        qmma_h(d0[2 * jj + 0], a0, bb[j2 * 4 + 0], bb[j2 * 4 + 1]);
                        qmma_h(d0[2 * jj + 1], a0, bb[j2 * 4 + 2], bb[j2 * 4 + 3]);
                        qmma_h(d1[2 * jj + 0], a1, bb[j2 * 4 + 0], bb[j2 * 4 + 1]);
                        qmma_h(d1[2 * jj + 1], a1, bb[j2 * 4 + 2], bb[j2 * 4 + 3]);
                    }
                }
            }

            // ---- epilogue after tap 8 ----
            if (tapc == 8) {
                __half2 h00 = __hadd2(*(const __half2*)&d0[0][0], bias_h2[s]);
                __half2 h01 = __hadd2(*(const __half2*)&d0[0][1], bias_h2[s]);
                __half2 h10 = __hadd2(*(const __half2*)&d1[0][0], bias_h2[s]);
                __half2 h11 = __hadd2(*(const __half2*)&d1[0][1], bias_h2[s]);
#pragma unroll
                for (int j = 1; j < 16; ++j) {
                    __half2 bj = bias_h2[4 * j + s];
                    h00 = __hmin2(h00, __hadd2(*(const __half2*)&d0[j][0], bj));
                    h01 = __hmin2(h01, __hadd2(*(const __half2*)&d0[j][1], bj));
                    h10 = __hmin2(h10, __hadd2(*(const __half2*)&d1[j][0], bj));
                    h11 = __hmin2(h11, __hadd2(*(const __half2*)&d1[j][1], bj));
                }
                float2 f;
                f = __half22float2(h00); float m00 = fminf(f.x, f.y);
                f = __half22float2(h01); float m01 = fminf(f.x, f.y);
                f = __half22float2(h10); float m10 = fminf(f.x, f.y);
                f = __half22float2(h11); float m11 = fminf(f.x, f.y);
#pragma unroll
                for (int off = 1; off <= 2; off <<= 1) {
                    m00 = fminf(m00, __shfl_xor_sync(0xffffffffu, m00, off));
                    m01 = fminf(m01, __shfl_xor_sync(0xffffffffu, m01, off));
                    m10 = fminf(m10, __shfl_xor_sync(0xffffffffu, m10, off));
                    m11 = fminf(m11, __shfl_xor_sync(0xffffffffu, m11, off));
                }
                if (s == 0) {
                    const int q = lane >> 2;
                    float* ob = out + (size_t)(gc / NT2) * HWn + (gc % NT2) * APIX;
                    ob[m0 + q]      = tanhf(tanhf(m00));
                    ob[m0 + q + 8]  = tanhf(tanhf(m01));
                    ob[m0 + q + 16] = tanhf(tanhf(m10));
                    ob[m0 + q + 24] = tanhf(tanhf(m11));
                }
            }
        }
        if (++tapc == 9) { tapc = 0; gc += NCTA; }
    }
}

extern "C" void kernel_launch(void* const* d_in, const int* in_sizes, int n_in,
                              void* d_out, int out_size) {
    const float* x    = (const float*)d_in[0];
    const float* wgt  = (const float*)d_in[1];
    const float* bias = (const float*)d_in[2];
    float* out = (float*)d_out;

    prep_w<<<(OCn * ICn * NTAPS + 255) / 256, 256>>>(wgt);
    dim3 pgrid(NTILES, Bn);
    prep_x<<<pgrid, 256>>>(x);

    cudaFuncSetAttribute(conv_mma, cudaFuncAttributeMaxDynamicSharedMemorySize, SM_TOTAL);
    conv_mma<<<NCTA, 256, SM_TOTAL>>>(bias, out);
}

// round 7
// speedup vs baseline: 1.1041x; 1.1041x over previous
#include <cuda_runtime.h>
#include <cuda_fp8.h>
#include <cuda_fp16.h>
#include <cstdint>
#include <math.h>

#define Bn   16
#define ICn  64
#define OCn  128
#define Hn   224
#define Wn   224
#define HWn  (Hn * Wn)
#define APIX 256                 // pixels per CTA
#define NT2  (HWn / APIX)        // 196
#define NTILES (HWn / 128)       // 392 (prep_x)
#define NTAPS 9

// fp8 scratch
__device__ uint8_t g_x8[(size_t)Bn * HWn * ICn];        // [b][hw][ic]
__device__ uint8_t g_w8[NTAPS * 4 * OCn * 16];          // [tap][chunk][oc][16]

__device__ __forceinline__ uint32_t smem_u32(const void* p) {
    uint32_t a;
    asm("{ .reg .u64 t; cvta.to.shared.u64 t, %1; cvt.u32.u64 %0, t; }"
        : "=r"(a) : "l"(p));
    return a;
}

// ---------------- prep kernels ----------------
__global__ void prep_w(const float* __restrict__ Wg) {
    int idx = blockIdx.x * 256 + threadIdx.x;
    if (idx < OCn * ICn * NTAPS) {
        int tap = idx % NTAPS;
        int ic  = (idx / NTAPS) % ICn;
        int oc  = idx / (NTAPS * ICn);
        uint8_t v = (uint8_t)__nv_cvt_float_to_fp8(Wg[idx], __NV_SATFINITE, __NV_E4M3);
        g_w8[((tap * 4 + (ic >> 4)) * OCn + oc) * 16 + (ic & 15)] = v;
    }
}

__global__ __launch_bounds__(256) void prep_x(const float* __restrict__ x) {
    __shared__ uint8_t s[128 * 65];
    const int tile = blockIdx.x, b = blockIdx.y;
    const int hw0 = tile * 128;
    const int t = threadIdx.x;
    const int ic = t >> 2, q = t & 3;

    const float4* src =
        (const float4*)(x + (size_t)b * ICn * HWn + (size_t)ic * HWn + hw0 + q * 32);
#pragma unroll
    for (int j = 0; j < 8; ++j) {
        float4 v = src[j];
        int pix = q * 32 + j * 4;
        s[(pix + 0) * 65 + ic] = (uint8_t)__nv_cvt_float_to_fp8(v.x, __NV_SATFINITE, __NV_E4M3);
        s[(pix + 1) * 65 + ic] = (uint8_t)__nv_cvt_float_to_fp8(v.y, __NV_SATFINITE, __NV_E4M3);
        s[(pix + 2) * 65 + ic] = (uint8_t)__nv_cvt_float_to_fp8(v.z, __NV_SATFINITE, __NV_E4M3);
        s[(pix + 3) * 65 + ic] = (uint8_t)__nv_cvt_float_to_fp8(v.w, __NV_SATFINITE, __NV_E4M3);
    }
    __syncthreads();

    const int pr = t >> 1, half = t & 1;
    uint32_t vv[8];
#pragma unroll
    for (int j = 0; j < 8; ++j) {
        int base = pr * 65 + half * 32 + j * 4;
        vv[j] = (uint32_t)s[base] | ((uint32_t)s[base + 1] << 8) |
                ((uint32_t)s[base + 2] << 16) | ((uint32_t)s[base + 3] << 24);
    }
    uint4* dst = (uint4*)(g_x8 + ((size_t)b * HWn + hw0 + pr) * 64 + half * 32);
    dst[0] = make_uint4(vv[0], vv[1], vv[2], vv[3]);
    dst[1] = make_uint4(vv[4], vv[5], vv[6], vv[7]);
}

// ---------------- main kernel ----------------
__device__ __forceinline__ void ldsm_x4(uint32_t* r, uint32_t addr) {
    asm volatile("ldmatrix.sync.aligned.m8n8.x4.shared.b16 {%0,%1,%2,%3}, [%4];"
                 : "=r"(r[0]), "=r"(r[1]), "=r"(r[2]), "=r"(r[3]) : "r"(addr));
}
__device__ __forceinline__ void qmma_h(uint32_t* d, const uint32_t* a,
                                       uint32_t b0, uint32_t b1) {
    asm volatile(
        "mma.sync.aligned.m16n8k32.row.col.f16.e4m3.e4m3.f16 "
        "{%0,%1}, {%2,%3,%4,%5}, {%6,%7}, {%0,%1};"
        : "+r"(d[0]), "+r"(d[1])
        : "r"(a[0]), "r"(a[1]), "r"(a[2]), "r"(a[3]), "r"(b0), "r"(b1));
}
__device__ __forceinline__ void cp16(uint32_t dst, const void* src, uint32_t sz) {
    asm volatile("cp.async.ca.shared.global [%0], [%1], 16, %2;"
                 :: "r"(dst), "l"(src), "r"(sz) : "memory");
}
__device__ __forceinline__ void cp16g(uint32_t dst, const void* src) {
    asm volatile("cp.async.cg.shared.global [%0], [%1], 16;"
                 :: "r"(dst), "l"(src) : "memory");
}
__device__ __forceinline__ void cp_commit() {
    asm volatile("cp.async.commit_group;" ::: "memory");
}
__device__ __forceinline__ void cp_wait0() {
    asm volatile("cp.async.wait_group 0;" ::: "memory");
}

// smem layout:
//   A: [2][4][APIX][16]   = 32768 B  @ 0        (double buffer, per tap)
//   B: [9][4][128][16]    = 73728 B  @ 32768    (resident whole kernel)
//   bias: 64 x half2      = 256 B    @ 106496
#define SM_A(buf, c, p)  ((uint32_t)(((buf) * 4 + (c)) * APIX + (p)) * 16)
#define SM_B(tap, c, r)  (32768u + (uint32_t)(((tap) * 4 + (c)) * 128 + (r)) * 16)
#define SM_BIAS 106496
#define SM_TOTAL 106752

__global__ __launch_bounds__(256, 2)
void conv_mma(const float* __restrict__ bias, float* __restrict__ out) {
    extern __shared__ __align__(16) uint8_t smem[];
    const __half2* bias_h2 = (const __half2*)(smem + SM_BIAS);

    const int tid = threadIdx.x;
    const int wid = tid >> 5;
    const int lane = tid & 31;
    const int tile = blockIdx.x;
    const int b = blockIdx.y;
    const uint32_t smem_base = smem_u32(smem);

    // ---- one-time: bias (half2) + all 9 taps of B -> smem ----
    if (tid < 64) {
        float2 bv = ((const float2*)bias)[tid];
        ((__half2*)(smem + SM_BIAS))[tid] = __floats2half2_rn(bv.x, bv.y);
    }
#pragma unroll
    for (int i = 0; i < 18; ++i)
        cp16g(smem_base + 32768u + (uint32_t)(i * 256 + tid) * 16,
              g_w8 + (i * 256 + tid) * 16);

    const int pix = tile * APIX + tid;
    const int h = pix / Wn;
    const int w = pix - h * Wn;
    const uint8_t* xb = g_x8 + (size_t)b * HWn * 64;

    // ---- issue A for tap 0 (same group as B; first wait covers both) ----
    {
        const int gh = h - 1, gw = w - 1;
        const uint32_t sz = (gh >= 0 && gw >= 0) ? 16u : 0u;
        const uint8_t* sp = xb + ((size_t)gh * Wn + gw) * 64;
#pragma unroll
        for (int c = 0; c < 4; ++c)
            cp16(smem_base + SM_A(0, c, tid), sp + c * 16, sz);
        cp_commit();
    }

    uint32_t d0[16][2], d1[16][2];
#pragma unroll
    for (int j = 0; j < 16; ++j) {
        d0[j][0] = d0[j][1] = 0u;
        d1[j][0] = d1[j][1] = 0u;
    }

    const int m0 = wid * 32;
    const int a_chunk_hi = (lane >= 16) ? 1 : 0;
    const int a_row0 = m0 + ((lane >> 3) & 1) * 8 + (lane & 7);
    const int a_row1 = a_row0 + 16;
    const int b_chunk_hi = (lane >> 3) & 1;
    const int b_row_off = ((lane >= 16) ? 8 : 0) + (lane & 7);
    const int s = lane & 3;

#pragma unroll 1
    for (int tap = 0; tap < NTAPS; ++tap) {
        const int buf = tap & 1;
        cp_wait0();
        __syncthreads();    // A_tap (and B on tap 0) visible; prev buf free

        // ---- issue A for tap+1 into other buffer ----
        if (tap < NTAPS - 1) {
            const int nt = tap + 1;
            const int gh = h + nt / 3 - 1;
            const int gw = w + nt % 3 - 1;
            const uint32_t sz =
                (gh >= 0 && gh < Hn && gw >= 0 && gw < Wn) ? 16u : 0u;
            const uint8_t* sp = xb + ((size_t)gh * Wn + gw) * 64;
#pragma unroll
            for (int c = 0; c < 4; ++c)
                cp16(smem_base + SM_A(buf ^ 1, c, tid), sp + c * 16, sz);
        }
        cp_commit();

        // ---- compute tap: 2 K32 steps, two m16 A-tiles share B frags ----
#pragma unroll
        for (int ks = 0; ks < 2; ++ks) {
            uint32_t a0[4], a1[4];
            ldsm_x4(a0, smem_base + SM_A(buf, 2 * ks + a_chunk_hi, a_row0));
            ldsm_x4(a1, smem_base + SM_A(buf, 2 * ks + a_chunk_hi, a_row1));
#pragma unroll
            for (int half = 0; half < 2; ++half) {
                uint32_t bb[16];
#pragma unroll
                for (int j2 = 0; j2 < 4; ++j2) {
                    int jj = half * 4 + j2;
                    ldsm_x4(&bb[j2 * 4],
                            smem_base + SM_B(tap, 2 * ks + b_chunk_hi,
                                             jj * 16 + b_row_off));
                }
#pragma unroll
                for (int j2 = 0; j2 < 4; ++j2) {
                    int jj = half * 4 + j2;
                    qmma_h(d0[2 * jj + 0], a0, bb[j2 * 4 + 0], bb[j2 * 4 + 1]);
                    qmma_h(d0[2 * jj + 1], a0, bb[j2 * 4 + 2], bb[j2 * 4 + 3]);
                    qmma_h(d1[2 * jj + 0], a1, bb[j2 * 4 + 0], bb[j2 * 4 + 1]);
                    qmma_h(d1[2 * jj + 1], a1, bb[j2 * 4 + 2], bb[j2 * 4 + 3]);
                }
            }
        }
    }

    // ---- epilogue: packed min over 128 OC, double tanh, store ----
    __half2 h00 = __hadd2(*(const __half2*)&d0[0][0], bias_h2[s]);
    __half2 h01 = __hadd2(*(const __half2*)&d0[0][1], bias_h2[s]);
    __half2 h10 = __hadd2(*(const __half2*)&d1[0][0], bias_h2[s]);
    __half2 h11 = __hadd2(*(const __half2*)&d1[0][1], bias_h2[s]);
#pragma unroll
    for (int j = 1; j < 16; ++j) {
        __half2 bj = bias_h2[4 * j + s];
        h00 = __hmin2(h00, __hadd2(*(const __half2*)&d0[j][0], bj));
        h01 = __hmin2(h01, __hadd2(*(const __half2*)&d0[j][1], bj));
        h10 = __hmin2(h10, __hadd2(*(const __half2*)&d1[j][0], bj));
        h11 = __hmin2(h11, __hadd2(*(const __half2*)&d1[j][1], bj));
    }
    float2 f;
    f = __half22float2(h00); float m00 = fminf(f.x, f.y);
    f = __half22float2(h01); float m01 = fminf(f.x, f.y);
    f = __half22float2(h10); float m10 = fminf(f.x, f.y);
    f = __half22float2(h11); float m11 = fminf(f.x, f.y);
#pragma unroll
    for (int off = 1; off <= 2; off <<= 1) {
        m00 = fminf(m00, __shfl_xor_sync(0xffffffffu, m00, off));
        m01 = fminf(m01, __shfl_xor_sync(0xffffffffu, m01, off));
        m10 = fminf(m10, __shfl_xor_sync(0xffffffffu, m10, off));
        m11 = fminf(m11, __shfl_xor_sync(0xffffffffu, m11, off));
    }
    if (s == 0) {
        const int q = lane >> 2;
        float* ob = out + (size_t)b * HWn + tile * APIX;
        ob[m0 + q]      = tanhf(tanhf(m00));
        ob[m0 + q + 8]  = tanhf(tanhf(m01));
        ob[m0 + q + 16] = tanhf(tanhf(m10));
        ob[m0 + q + 24] = tanhf(tanhf(m11));
    }
}

extern "C" void kernel_launch(void* const* d_in, const int* in_sizes, int n_in,
                              void* d_out, int out_size) {
    const float* x    = (const float*)d_in[0];
    const float* wgt  = (const float*)d_in[1];
    const float* bias = (const float*)d_in[2];
    float* out = (float*)d_out;

    prep_w<<<(OCn * ICn * NTAPS + 255) / 256, 256>>>(wgt);
    dim3 pgrid(NTILES, Bn);
    prep_x<<<pgrid, 256>>>(x);

    cudaFuncSetAttribute(conv_mma, cudaFuncAttributeMaxDynamicSharedMemorySize, SM_TOTAL);
    dim3 grid(NT2, Bn);   // 196 x 16
    conv_mma<<<grid, 256, SM_TOTAL>>>(bias, out);
}